// round 3
// baseline (speedup 1.0000x reference)
#include <cuda_runtime.h>
#include <cuda_bf16.h>
#include <cstddef>

// ---------------------------------------------------------------------------
// Scratch (device globals — no runtime allocation allowed)
// ---------------------------------------------------------------------------
__device__ float g_h  [4096 * 1024];   // LN output (reused for LN1 and LN2)
__device__ float g_qkv[4096 * 3072];   // QKV
__device__ float g_y  [4096 * 1024];   // attention output
__device__ float g_x1 [4096 * 1024];   // x + attn proj (residual 1)
__device__ float g_fc [4096 * 4096];   // FC (post-GELU)

// ---------------------------------------------------------------------------
// GELU (tanh approx), overflow-safe:  gelu(v) = v * (1 - 1/(e^{2u}+1))
// ---------------------------------------------------------------------------
__device__ __forceinline__ float gelu_tanh(float v) {
    float u = 0.7978845608028654f * fmaf(0.044715f * v * v, v, v);
    float e = __expf(2.0f * u);
    return v * (1.0f - 1.0f / (e + 1.0f));
}

// ---------------------------------------------------------------------------
// LayerNorm: one block per row of 1024, 256 threads, float4
// ---------------------------------------------------------------------------
__global__ void __launch_bounds__(256) ln_kernel(
    const float* __restrict__ x, const float* __restrict__ g,
    const float* __restrict__ b, float* __restrict__ o)
{
    const int row = blockIdx.x;
    const int tid = threadIdx.x;
    float4 v = reinterpret_cast<const float4*>(x + (size_t)row * 1024)[tid];
    float s  = v.x + v.y + v.z + v.w;
    float ss = v.x * v.x + v.y * v.y + v.z * v.z + v.w * v.w;
    #pragma unroll
    for (int off = 16; off; off >>= 1) {
        s  += __shfl_down_sync(0xffffffffu, s, off);
        ss += __shfl_down_sync(0xffffffffu, ss, off);
    }
    __shared__ float ws[8], wss[8];
    const int wid = tid >> 5, lane = tid & 31;
    if (lane == 0) { ws[wid] = s; wss[wid] = ss; }
    __syncthreads();
    s = 0.f; ss = 0.f;
    #pragma unroll
    for (int w = 0; w < 8; w++) { s += ws[w]; ss += wss[w]; }
    const float mean = s * (1.0f / 1024.0f);
    const float var  = ss * (1.0f / 1024.0f) - mean * mean;
    const float rstd = rsqrtf(var + 1e-5f);
    float4 gv = reinterpret_cast<const float4*>(g)[tid];
    float4 bv = reinterpret_cast<const float4*>(b)[tid];
    float4 r;
    r.x = (v.x - mean) * rstd * gv.x + bv.x;
    r.y = (v.y - mean) * rstd * gv.y + bv.y;
    r.z = (v.z - mean) * rstd * gv.z + bv.z;
    r.w = (v.w - mean) * rstd * gv.w + bv.w;
    reinterpret_cast<float4*>(o + (size_t)row * 1024)[tid] = r;
}

// ---------------------------------------------------------------------------
// SGEMM: C[M,N] = A[M,K] @ B[K,N] + bias (+Res / +GELU per EPI)
//   EPI 0: bias;  EPI 1: bias + residual;  EPI 2: bias + GELU
// 128x128x16 tile, 8x8 per thread, 256 threads, double-buffered SMEM with
// register prefetch. M,N,K assumed multiples of tile dims (true here).
// ---------------------------------------------------------------------------
template <int EPI>
__global__ void __launch_bounds__(256, 2) sgemm_kernel(
    const float* __restrict__ A, const float* __restrict__ B,
    const float* __restrict__ bias, const float* __restrict__ Res,
    float* __restrict__ C, int M, int N, int K)
{
    __shared__ float As[2][16][128];
    __shared__ float Bs[2][16][128];

    const int tid = threadIdx.x;
    const int block_row = blockIdx.y * 128;
    const int block_col = blockIdx.x * 128;
    const int trow = (tid >> 4) * 8;       // 0..120
    const int tcol = (tid & 15) * 8;       // 0..120

    // loader mappings
    const int a_r0 = tid >> 2;             // 0..63
    const int a_c0 = (tid & 3) * 4;        // 0,4,8,12
    const int b_r0 = tid >> 5;             // 0..7
    const int b_c0 = (tid & 31) * 4;       // 0..124

    const int nTiles = K >> 4;

    // prologue: tile 0 -> buffer 0
    {
        #pragma unroll
        for (int i = 0; i < 2; i++) {
            const int r = a_r0 + i * 64;
            float4 av = *reinterpret_cast<const float4*>(
                A + (size_t)(block_row + r) * K + a_c0);
            As[0][a_c0 + 0][r] = av.x;
            As[0][a_c0 + 1][r] = av.y;
            As[0][a_c0 + 2][r] = av.z;
            As[0][a_c0 + 3][r] = av.w;
        }
        #pragma unroll
        for (int i = 0; i < 2; i++) {
            const int r = b_r0 + i * 8;
            float4 bv = *reinterpret_cast<const float4*>(
                B + (size_t)r * N + block_col + b_c0);
            *reinterpret_cast<float4*>(&Bs[0][r][b_c0]) = bv;
        }
    }
    __syncthreads();

    float acc[8][8];
    #pragma unroll
    for (int i = 0; i < 8; i++)
        #pragma unroll
        for (int j = 0; j < 8; j++) acc[i][j] = 0.f;

    for (int t = 0; t < nTiles; t++) {
        const int cur = t & 1, nxt = cur ^ 1;
        float4 aReg[2], bReg[2];
        const bool has = (t + 1 < nTiles);
        if (has) {
            const int k0 = (t + 1) << 4;
            #pragma unroll
            for (int i = 0; i < 2; i++) {
                aReg[i] = *reinterpret_cast<const float4*>(
                    A + (size_t)(block_row + a_r0 + i * 64) * K + k0 + a_c0);
                bReg[i] = *reinterpret_cast<const float4*>(
                    B + (size_t)(k0 + b_r0 + i * 8) * N + block_col + b_c0);
            }
        }

        #pragma unroll
        for (int k = 0; k < 16; k++) {
            float4 a0 = *reinterpret_cast<const float4*>(&As[cur][k][trow]);
            float4 a1 = *reinterpret_cast<const float4*>(&As[cur][k][trow + 4]);
            float4 b0 = *reinterpret_cast<const float4*>(&Bs[cur][k][tcol]);
            float4 b1 = *reinterpret_cast<const float4*>(&Bs[cur][k][tcol + 4]);
            const float af[8] = {a0.x, a0.y, a0.z, a0.w, a1.x, a1.y, a1.z, a1.w};
            const float bf[8] = {b0.x, b0.y, b0.z, b0.w, b1.x, b1.y, b1.z, b1.w};
            #pragma unroll
            for (int i = 0; i < 8; i++)
                #pragma unroll
                for (int j = 0; j < 8; j++)
                    acc[i][j] = fmaf(af[i], bf[j], acc[i][j]);
        }

        if (has) {
            #pragma unroll
            for (int i = 0; i < 2; i++) {
                const int r = a_r0 + i * 64;
                As[nxt][a_c0 + 0][r] = aReg[i].x;
                As[nxt][a_c0 + 1][r] = aReg[i].y;
                As[nxt][a_c0 + 2][r] = aReg[i].z;
                As[nxt][a_c0 + 3][r] = aReg[i].w;
                *reinterpret_cast<float4*>(&Bs[nxt][b_r0 + i * 8][b_c0]) = bReg[i];
            }
        }
        __syncthreads();
    }

    // epilogue
    #pragma unroll
    for (int i = 0; i < 8; i++) {
        const int row = block_row + trow + i;
        #pragma unroll
        for (int j4 = 0; j4 < 2; j4++) {
            const int col = block_col + tcol + j4 * 4;
            float4 v;
            v.x = acc[i][j4 * 4 + 0] + bias[col + 0];
            v.y = acc[i][j4 * 4 + 1] + bias[col + 1];
            v.z = acc[i][j4 * 4 + 2] + bias[col + 2];
            v.w = acc[i][j4 * 4 + 3] + bias[col + 3];
            if (EPI == 1) {
                float4 r = *reinterpret_cast<const float4*>(
                    Res + (size_t)row * N + col);
                v.x += r.x; v.y += r.y; v.z += r.z; v.w += r.w;
            }
            if (EPI == 2) {
                v.x = gelu_tanh(v.x); v.y = gelu_tanh(v.y);
                v.z = gelu_tanh(v.z); v.w = gelu_tanh(v.w);
            }
            *reinterpret_cast<float4*>(C + (size_t)row * N + col) = v;
        }
    }
}

// ---------------------------------------------------------------------------
// Flash attention (fp32, causal): 64x64 Q/KV tiles, online softmax.
// grid = (T/64, B*H), 256 threads. qkv layout [B,T,3C], head h at cols h*64.
// Dynamic SMEM = 67584 bytes.
// ---------------------------------------------------------------------------
__global__ void __launch_bounds__(256) attn_kernel(
    const float* __restrict__ qkv, float* __restrict__ y)
{
    const int T = 2048, C3 = 3072;
    extern __shared__ float sm[];
    float* Qs   = sm;                 // [64][64]
    float* KsT  = Qs  + 64 * 64;      // [64 d][68]  (d-major, padded)
    float* Vs   = KsT + 64 * 68;      // [64][64]
    float* Ss   = Vs  + 64 * 64;      // [64][65]    (padded)
    float* m_s  = Ss  + 64 * 65;      // [64]
    float* l_s  = m_s + 64;           // [64]
    float* al_s = l_s + 64;           // [64]

    const int q0 = blockIdx.x * 64;
    const int bh = blockIdx.y;
    const int bb = bh >> 4, hh = bh & 15;
    const float* qbase = qkv + (size_t)bb * T * C3 + hh * 64;
    const float* kbase = qbase + 1024;
    const float* vbase = qbase + 2048;

    const int tid = threadIdx.x;
    const int tx = tid & 15, ty = tid >> 4;
    const int r0 = ty * 4, c0 = tx * 4;

    // load Q (scaled by 1/sqrt(64))
    #pragma unroll
    for (int i = 0; i < 4; i++) {
        const int v = tid + i * 256;
        const int r = v >> 4, d4 = (v & 15) * 4;
        float4 q = *reinterpret_cast<const float4*>(
            qbase + (size_t)(q0 + r) * C3 + d4);
        q.x *= 0.125f; q.y *= 0.125f; q.z *= 0.125f; q.w *= 0.125f;
        *reinterpret_cast<float4*>(Qs + r * 64 + d4) = q;
    }
    if (tid < 64) { m_s[tid] = -1e30f; l_s[tid] = 0.f; }

    float o[4][4];
    #pragma unroll
    for (int i = 0; i < 4; i++)
        #pragma unroll
        for (int j = 0; j < 4; j++) o[i][j] = 0.f;

    const int ntiles = (q0 >> 6) + 1;
    for (int jt = 0; jt < ntiles; jt++) {
        const int j0 = jt * 64;
        __syncthreads();
        // K -> KsT[d][j] (lanes walk j: conflict-free SMEM stores)
        #pragma unroll
        for (int i = 0; i < 4; i++) {
            const int v = tid + i * 256;
            const int jr = v & 63, d4 = (v >> 6) * 4;
            float4 kk = *reinterpret_cast<const float4*>(
                kbase + (size_t)(j0 + jr) * C3 + d4);
            KsT[(d4 + 0) * 68 + jr] = kk.x;
            KsT[(d4 + 1) * 68 + jr] = kk.y;
            KsT[(d4 + 2) * 68 + jr] = kk.z;
            KsT[(d4 + 3) * 68 + jr] = kk.w;
        }
        // V straight (coalesced global, conflict-free stores)
        #pragma unroll
        for (int i = 0; i < 4; i++) {
            const int v = tid + i * 256;
            const int jr = v >> 4, d4 = (v & 15) * 4;
            float4 vv = *reinterpret_cast<const float4*>(
                vbase + (size_t)(j0 + jr) * C3 + d4);
            *reinterpret_cast<float4*>(Vs + jr * 64 + d4) = vv;
        }
        __syncthreads();

        // S = Q K^T (4x4 per thread)
        float s4[4][4];
        #pragma unroll
        for (int i = 0; i < 4; i++)
            #pragma unroll
            for (int j = 0; j < 4; j++) s4[i][j] = 0.f;
        #pragma unroll 8
        for (int d = 0; d < 64; d++) {
            const float4 kv = *reinterpret_cast<const float4*>(KsT + d * 68 + c0);
            const float q0v = Qs[(r0 + 0) * 64 + d];
            const float q1v = Qs[(r0 + 1) * 64 + d];
            const float q2v = Qs[(r0 + 2) * 64 + d];
            const float q3v = Qs[(r0 + 3) * 64 + d];
            s4[0][0] = fmaf(q0v, kv.x, s4[0][0]); s4[0][1] = fmaf(q0v, kv.y, s4[0][1]);
            s4[0][2] = fmaf(q0v, kv.z, s4[0][2]); s4[0][3] = fmaf(q0v, kv.w, s4[0][3]);
            s4[1][0] = fmaf(q1v, kv.x, s4[1][0]); s4[1][1] = fmaf(q1v, kv.y, s4[1][1]);
            s4[1][2] = fmaf(q1v, kv.z, s4[1][2]); s4[1][3] = fmaf(q1v, kv.w, s4[1][3]);
            s4[2][0] = fmaf(q2v, kv.x, s4[2][0]); s4[2][1] = fmaf(q2v, kv.y, s4[2][1]);
            s4[2][2] = fmaf(q2v, kv.z, s4[2][2]); s4[2][3] = fmaf(q2v, kv.w, s4[2][3]);
            s4[3][0] = fmaf(q3v, kv.x, s4[3][0]); s4[3][1] = fmaf(q3v, kv.y, s4[3][1]);
            s4[3][2] = fmaf(q3v, kv.z, s4[3][2]); s4[3][3] = fmaf(q3v, kv.w, s4[3][3]);
        }
        // causal mask on diagonal tile
        if (j0 == q0) {
            #pragma unroll
            for (int rr = 0; rr < 4; rr++)
                #pragma unroll
                for (int cc = 0; cc < 4; cc++)
                    if (c0 + cc > r0 + rr) s4[rr][cc] = -1e30f;
        }
        #pragma unroll
        for (int rr = 0; rr < 4; rr++)
            #pragma unroll
            for (int cc = 0; cc < 4; cc++)
                Ss[(r0 + rr) * 65 + c0 + cc] = s4[rr][cc];
        __syncthreads();

        // online softmax stats: 4 threads per row
        {
            const int row = tid >> 2, part = tid & 3;
            float* srow = Ss + row * 65 + part * 16;
            float mx = -1e30f;
            #pragma unroll
            for (int j = 0; j < 16; j++) mx = fmaxf(mx, srow[j]);
            mx = fmaxf(mx, __shfl_xor_sync(0xffffffffu, mx, 1));
            mx = fmaxf(mx, __shfl_xor_sync(0xffffffffu, mx, 2));
            const float m_old = m_s[row];
            const float m_new = fmaxf(m_old, mx);
            float sum = 0.f;
            #pragma unroll
            for (int j = 0; j < 16; j++) {
                const float p = __expf(srow[j] - m_new);
                srow[j] = p;
                sum += p;
            }
            sum += __shfl_xor_sync(0xffffffffu, sum, 1);
            sum += __shfl_xor_sync(0xffffffffu, sum, 2);
            if (part == 0) {
                const float alpha = __expf(m_old - m_new);
                al_s[row] = alpha;
                m_s[row]  = m_new;
                l_s[row]  = l_s[row] * alpha + sum;
            }
        }
        __syncthreads();

        // O = O*alpha + P @ V
        const float a0 = al_s[r0 + 0], a1 = al_s[r0 + 1];
        const float a2 = al_s[r0 + 2], a3 = al_s[r0 + 3];
        #pragma unroll
        for (int cc = 0; cc < 4; cc++) {
            o[0][cc] *= a0; o[1][cc] *= a1; o[2][cc] *= a2; o[3][cc] *= a3;
        }
        #pragma unroll 8
        for (int j = 0; j < 64; j++) {
            const float4 vv = *reinterpret_cast<const float4*>(Vs + j * 64 + c0);
            const float p0 = Ss[(r0 + 0) * 65 + j];
            const float p1 = Ss[(r0 + 1) * 65 + j];
            const float p2 = Ss[(r0 + 2) * 65 + j];
            const float p3 = Ss[(r0 + 3) * 65 + j];
            o[0][0] = fmaf(p0, vv.x, o[0][0]); o[0][1] = fmaf(p0, vv.y, o[0][1]);
            o[0][2] = fmaf(p0, vv.z, o[0][2]); o[0][3] = fmaf(p0, vv.w, o[0][3]);
            o[1][0] = fmaf(p1, vv.x, o[1][0]); o[1][1] = fmaf(p1, vv.y, o[1][1]);
            o[1][2] = fmaf(p1, vv.z, o[1][2]); o[1][3] = fmaf(p1, vv.w, o[1][3]);
            o[2][0] = fmaf(p2, vv.x, o[2][0]); o[2][1] = fmaf(p2, vv.y, o[2][1]);
            o[2][2] = fmaf(p2, vv.z, o[2][2]); o[2][3] = fmaf(p2, vv.w, o[2][3]);
            o[3][0] = fmaf(p3, vv.x, o[3][0]); o[3][1] = fmaf(p3, vv.y, o[3][1]);
            o[3][2] = fmaf(p3, vv.z, o[3][2]); o[3][3] = fmaf(p3, vv.w, o[3][3]);
        }
    }

    // finalize and write y[B,T,C]
    #pragma unroll
    for (int rr = 0; rr < 4; rr++) {
        const float inv = 1.0f / l_s[r0 + rr];
        float4 ov = make_float4(o[rr][0] * inv, o[rr][1] * inv,
                                o[rr][2] * inv, o[rr][3] * inv);
        *reinterpret_cast<float4*>(
            y + ((size_t)bb * T + q0 + r0 + rr) * 1024 + hh * 64 + c0) = ov;
    }
}

// ---------------------------------------------------------------------------
// Launch
// ---------------------------------------------------------------------------
extern "C" void kernel_launch(void* const* d_in, const int* in_sizes, int n_in,
                              void* d_out, int out_size)
{
    const float* x      = (const float*)d_in[0];
    const float* ln1_g  = (const float*)d_in[1];
    const float* ln1_b  = (const float*)d_in[2];
    const float* W_attn = (const float*)d_in[3];
    const float* b_attn = (const float*)d_in[4];
    const float* W_o    = (const float*)d_in[5];
    const float* b_o    = (const float*)d_in[6];
    const float* ln2_g  = (const float*)d_in[7];
    const float* ln2_b  = (const float*)d_in[8];
    const float* W_fc   = (const float*)d_in[9];
    const float* b_fc   = (const float*)d_in[10];
    const float* W_fc2  = (const float*)d_in[11];
    const float* b_fc2  = (const float*)d_in[12];
    float* out = (float*)d_out;

    float *h, *qkv, *yb, *x1, *fc;
    cudaGetSymbolAddress((void**)&h,   g_h);
    cudaGetSymbolAddress((void**)&qkv, g_qkv);
    cudaGetSymbolAddress((void**)&yb,  g_y);
    cudaGetSymbolAddress((void**)&x1,  g_x1);
    cudaGetSymbolAddress((void**)&fc,  g_fc);

    const int ATTN_SMEM = 67584;
    cudaFuncSetAttribute(attn_kernel,
                         cudaFuncAttributeMaxDynamicSharedMemorySize, ATTN_SMEM);

    const int M = 4096;  // B*T

    // 1. LN1
    ln_kernel<<<M, 256>>>(x, ln1_g, ln1_b, h);
    // 2. QKV = h @ W_attn + b_attn   [4096, 3072]
    sgemm_kernel<0><<<dim3(3072 / 128, M / 128), 256>>>(
        h, W_attn, b_attn, nullptr, qkv, M, 3072, 1024);
    // 3. attention -> y [4096, 1024]
    attn_kernel<<<dim3(32, 32), 256, ATTN_SMEM>>>(qkv, yb);
    // 4. x1 = x + y @ W_o + b_o
    sgemm_kernel<1><<<dim3(1024 / 128, M / 128), 256>>>(
        yb, W_o, b_o, x, x1, M, 1024, 1024);
    // 5. LN2
    ln_kernel<<<M, 256>>>(x1, ln2_g, ln2_b, h);
    // 6. fc = gelu(h @ W_fc + b_fc)  [4096, 4096]
    sgemm_kernel<2><<<dim3(4096 / 128, M / 128), 256>>>(
        h, W_fc, b_fc, nullptr, fc, M, 4096, 1024);
    // 7. out = x1 + fc @ W_fc2 + b_fc2
    sgemm_kernel<1><<<dim3(1024 / 128, M / 128), 256>>>(
        fc, W_fc2, b_fc2, x1, out, M, 1024, 4096);
}

// round 4
// speedup vs baseline: 1.0013x; 1.0013x over previous
#include <cuda_runtime.h>
#include <cuda_bf16.h>
#include <cstddef>

// ---------------------------------------------------------------------------
// Scratch (device globals — no runtime allocation allowed)
// ---------------------------------------------------------------------------
__device__ float g_h  [4096 * 1024];   // LN output (reused for LN1 and LN2)
__device__ float g_qkv[4096 * 3072];   // QKV
__device__ float g_y  [4096 * 1024];   // attention output
__device__ float g_x1 [4096 * 1024];   // x + attn proj (residual 1)
__device__ float g_fc [4096 * 4096];   // FC (post-GELU)

// ---------------------------------------------------------------------------
// GELU (tanh approx), overflow-safe:  gelu(v) = v * (1 - 1/(e^{2u}+1))
// ---------------------------------------------------------------------------
__device__ __forceinline__ float gelu_tanh(float v) {
    float u = 0.7978845608028654f * fmaf(0.044715f * v * v, v, v);
    float e = __expf(2.0f * u);
    return v * (1.0f - 1.0f / (e + 1.0f));
}

// ---------------------------------------------------------------------------
// LayerNorm: one block per row of 1024, 256 threads, float4
// ---------------------------------------------------------------------------
__global__ void __launch_bounds__(256) ln_kernel(
    const float* __restrict__ x, const float* __restrict__ g,
    const float* __restrict__ b, float* __restrict__ o)
{
    const int row = blockIdx.x;
    const int tid = threadIdx.x;
    float4 v = reinterpret_cast<const float4*>(x + (size_t)row * 1024)[tid];
    float s  = v.x + v.y + v.z + v.w;
    float ss = v.x * v.x + v.y * v.y + v.z * v.z + v.w * v.w;
    #pragma unroll
    for (int off = 16; off; off >>= 1) {
        s  += __shfl_down_sync(0xffffffffu, s, off);
        ss += __shfl_down_sync(0xffffffffu, ss, off);
    }
    __shared__ float ws[8], wss[8];
    const int wid = tid >> 5, lane = tid & 31;
    if (lane == 0) { ws[wid] = s; wss[wid] = ss; }
    __syncthreads();
    s = 0.f; ss = 0.f;
    #pragma unroll
    for (int w = 0; w < 8; w++) { s += ws[w]; ss += wss[w]; }
    const float mean = s * (1.0f / 1024.0f);
    const float var  = ss * (1.0f / 1024.0f) - mean * mean;
    const float rstd = rsqrtf(var + 1e-5f);
    float4 gv = reinterpret_cast<const float4*>(g)[tid];
    float4 bv = reinterpret_cast<const float4*>(b)[tid];
    float4 r;
    r.x = (v.x - mean) * rstd * gv.x + bv.x;
    r.y = (v.y - mean) * rstd * gv.y + bv.y;
    r.z = (v.z - mean) * rstd * gv.z + bv.z;
    r.w = (v.w - mean) * rstd * gv.w + bv.w;
    reinterpret_cast<float4*>(o + (size_t)row * 1024)[tid] = r;
}

// ---------------------------------------------------------------------------
// SGEMM: C[M,N] = A[M,K] @ B[K,N] + bias (+Res / +GELU per EPI)
//   EPI 0: bias;  EPI 1: bias + residual;  EPI 2: bias + GELU
// 128x128x16 tile, 8x8 per thread, 256 threads, double-buffered SMEM with
// register prefetch. M,N,K assumed multiples of tile dims (true here).
// ---------------------------------------------------------------------------
template <int EPI>
__global__ void __launch_bounds__(256, 2) sgemm_kernel(
    const float* __restrict__ A, const float* __restrict__ B,
    const float* __restrict__ bias, const float* __restrict__ Res,
    float* __restrict__ C, int M, int N, int K)
{
    __shared__ float As[2][16][128];
    __shared__ float Bs[2][16][128];

    const int tid = threadIdx.x;
    const int block_row = blockIdx.y * 128;
    const int block_col = blockIdx.x * 128;
    const int trow = (tid >> 4) * 8;       // 0..120
    const int tcol = (tid & 15) * 8;       // 0..120

    // loader mappings
    const int a_r0 = tid >> 2;             // 0..63
    const int a_c0 = (tid & 3) * 4;        // 0,4,8,12
    const int b_r0 = tid >> 5;             // 0..7
    const int b_c0 = (tid & 31) * 4;       // 0..124

    const int nTiles = K >> 4;

    // prologue: tile 0 -> buffer 0
    {
        #pragma unroll
        for (int i = 0; i < 2; i++) {
            const int r = a_r0 + i * 64;
            float4 av = *reinterpret_cast<const float4*>(
                A + (size_t)(block_row + r) * K + a_c0);
            As[0][a_c0 + 0][r] = av.x;
            As[0][a_c0 + 1][r] = av.y;
            As[0][a_c0 + 2][r] = av.z;
            As[0][a_c0 + 3][r] = av.w;
        }
        #pragma unroll
        for (int i = 0; i < 2; i++) {
            const int r = b_r0 + i * 8;
            float4 bv = *reinterpret_cast<const float4*>(
                B + (size_t)r * N + block_col + b_c0);
            *reinterpret_cast<float4*>(&Bs[0][r][b_c0]) = bv;
        }
    }
    __syncthreads();

    float acc[8][8];
    #pragma unroll
    for (int i = 0; i < 8; i++)
        #pragma unroll
        for (int j = 0; j < 8; j++) acc[i][j] = 0.f;

    for (int t = 0; t < nTiles; t++) {
        const int cur = t & 1, nxt = cur ^ 1;
        float4 aReg[2], bReg[2];
        const bool has = (t + 1 < nTiles);
        if (has) {
            const int k0 = (t + 1) << 4;
            #pragma unroll
            for (int i = 0; i < 2; i++) {
                aReg[i] = *reinterpret_cast<const float4*>(
                    A + (size_t)(block_row + a_r0 + i * 64) * K + k0 + a_c0);
                bReg[i] = *reinterpret_cast<const float4*>(
                    B + (size_t)(k0 + b_r0 + i * 8) * N + block_col + b_c0);
            }
        }

        #pragma unroll
        for (int k = 0; k < 16; k++) {
            float4 a0 = *reinterpret_cast<const float4*>(&As[cur][k][trow]);
            float4 a1 = *reinterpret_cast<const float4*>(&As[cur][k][trow + 4]);
            float4 b0 = *reinterpret_cast<const float4*>(&Bs[cur][k][tcol]);
            float4 b1 = *reinterpret_cast<const float4*>(&Bs[cur][k][tcol + 4]);
            const float af[8] = {a0.x, a0.y, a0.z, a0.w, a1.x, a1.y, a1.z, a1.w};
            const float bf[8] = {b0.x, b0.y, b0.z, b0.w, b1.x, b1.y, b1.z, b1.w};
            #pragma unroll
            for (int i = 0; i < 8; i++)
                #pragma unroll
                for (int j = 0; j < 8; j++)
                    acc[i][j] = fmaf(af[i], bf[j], acc[i][j]);
        }

        if (has) {
            #pragma unroll
            for (int i = 0; i < 2; i++) {
                const int r = a_r0 + i * 64;
                As[nxt][a_c0 + 0][r] = aReg[i].x;
                As[nxt][a_c0 + 1][r] = aReg[i].y;
                As[nxt][a_c0 + 2][r] = aReg[i].z;
                As[nxt][a_c0 + 3][r] = aReg[i].w;
                *reinterpret_cast<float4*>(&Bs[nxt][b_r0 + i * 8][b_c0]) = bReg[i];
            }
        }
        __syncthreads();
    }

    // epilogue
    #pragma unroll
    for (int i = 0; i < 8; i++) {
        const int row = block_row + trow + i;
        #pragma unroll
        for (int j4 = 0; j4 < 2; j4++) {
            const int col = block_col + tcol + j4 * 4;
            float4 v;
            v.x = acc[i][j4 * 4 + 0] + bias[col + 0];
            v.y = acc[i][j4 * 4 + 1] + bias[col + 1];
            v.z = acc[i][j4 * 4 + 2] + bias[col + 2];
            v.w = acc[i][j4 * 4 + 3] + bias[col + 3];
            if (EPI == 1) {
                float4 r = *reinterpret_cast<const float4*>(
                    Res + (size_t)row * N + col);
                v.x += r.x; v.y += r.y; v.z += r.z; v.w += r.w;
            }
            if (EPI == 2) {
                v.x = gelu_tanh(v.x); v.y = gelu_tanh(v.y);
                v.z = gelu_tanh(v.z); v.w = gelu_tanh(v.w);
            }
            *reinterpret_cast<float4*>(C + (size_t)row * N + col) = v;
        }
    }
}

// ---------------------------------------------------------------------------
// Flash attention (fp32, causal): 64x64 Q/KV tiles, online softmax.
// grid = (T/64, B*H), 256 threads. qkv layout [B,T,3C], head h at cols h*64.
// Dynamic SMEM = 67584 bytes.
// ---------------------------------------------------------------------------
__global__ void __launch_bounds__(256) attn_kernel(
    const float* __restrict__ qkv, float* __restrict__ y)
{
    const int T = 2048, C3 = 3072;
    extern __shared__ float sm[];
    float* Qs   = sm;                 // [64][64]
    float* KsT  = Qs  + 64 * 64;      // [64 d][68]  (d-major, padded)
    float* Vs   = KsT + 64 * 68;      // [64][64]
    float* Ss   = Vs  + 64 * 64;      // [64][65]    (padded)
    float* m_s  = Ss  + 64 * 65;      // [64]
    float* l_s  = m_s + 64;           // [64]
    float* al_s = l_s + 64;           // [64]

    const int q0 = blockIdx.x * 64;
    const int bh = blockIdx.y;
    const int bb = bh >> 4, hh = bh & 15;
    const float* qbase = qkv + (size_t)bb * T * C3 + hh * 64;
    const float* kbase = qbase + 1024;
    const float* vbase = qbase + 2048;

    const int tid = threadIdx.x;
    const int tx = tid & 15, ty = tid >> 4;
    const int r0 = ty * 4, c0 = tx * 4;

    // load Q (scaled by 1/sqrt(64))
    #pragma unroll
    for (int i = 0; i < 4; i++) {
        const int v = tid + i * 256;
        const int r = v >> 4, d4 = (v & 15) * 4;
        float4 q = *reinterpret_cast<const float4*>(
            qbase + (size_t)(q0 + r) * C3 + d4);
        q.x *= 0.125f; q.y *= 0.125f; q.z *= 0.125f; q.w *= 0.125f;
        *reinterpret_cast<float4*>(Qs + r * 64 + d4) = q;
    }
    if (tid < 64) { m_s[tid] = -1e30f; l_s[tid] = 0.f; }

    float o[4][4];
    #pragma unroll
    for (int i = 0; i < 4; i++)
        #pragma unroll
        for (int j = 0; j < 4; j++) o[i][j] = 0.f;

    const int ntiles = (q0 >> 6) + 1;
    for (int jt = 0; jt < ntiles; jt++) {
        const int j0 = jt * 64;
        __syncthreads();
        // K -> KsT[d][j] (lanes walk j: conflict-free SMEM stores)
        #pragma unroll
        for (int i = 0; i < 4; i++) {
            const int v = tid + i * 256;
            const int jr = v & 63, d4 = (v >> 6) * 4;
            float4 kk = *reinterpret_cast<const float4*>(
                kbase + (size_t)(j0 + jr) * C3 + d4);
            KsT[(d4 + 0) * 68 + jr] = kk.x;
            KsT[(d4 + 1) * 68 + jr] = kk.y;
            KsT[(d4 + 2) * 68 + jr] = kk.z;
            KsT[(d4 + 3) * 68 + jr] = kk.w;
        }
        // V straight (coalesced global, conflict-free stores)
        #pragma unroll
        for (int i = 0; i < 4; i++) {
            const int v = tid + i * 256;
            const int jr = v >> 4, d4 = (v & 15) * 4;
            float4 vv = *reinterpret_cast<const float4*>(
                vbase + (size_t)(j0 + jr) * C3 + d4);
            *reinterpret_cast<float4*>(Vs + jr * 64 + d4) = vv;
        }
        __syncthreads();

        // S = Q K^T (4x4 per thread)
        float s4[4][4];
        #pragma unroll
        for (int i = 0; i < 4; i++)
            #pragma unroll
            for (int j = 0; j < 4; j++) s4[i][j] = 0.f;
        #pragma unroll 8
        for (int d = 0; d < 64; d++) {
            const float4 kv = *reinterpret_cast<const float4*>(KsT + d * 68 + c0);
            const float q0v = Qs[(r0 + 0) * 64 + d];
            const float q1v = Qs[(r0 + 1) * 64 + d];
            const float q2v = Qs[(r0 + 2) * 64 + d];
            const float q3v = Qs[(r0 + 3) * 64 + d];
            s4[0][0] = fmaf(q0v, kv.x, s4[0][0]); s4[0][1] = fmaf(q0v, kv.y, s4[0][1]);
            s4[0][2] = fmaf(q0v, kv.z, s4[0][2]); s4[0][3] = fmaf(q0v, kv.w, s4[0][3]);
            s4[1][0] = fmaf(q1v, kv.x, s4[1][0]); s4[1][1] = fmaf(q1v, kv.y, s4[1][1]);
            s4[1][2] = fmaf(q1v, kv.z, s4[1][2]); s4[1][3] = fmaf(q1v, kv.w, s4[1][3]);
            s4[2][0] = fmaf(q2v, kv.x, s4[2][0]); s4[2][1] = fmaf(q2v, kv.y, s4[2][1]);
            s4[2][2] = fmaf(q2v, kv.z, s4[2][2]); s4[2][3] = fmaf(q2v, kv.w, s4[2][3]);
            s4[3][0] = fmaf(q3v, kv.x, s4[3][0]); s4[3][1] = fmaf(q3v, kv.y, s4[3][1]);
            s4[3][2] = fmaf(q3v, kv.z, s4[3][2]); s4[3][3] = fmaf(q3v, kv.w, s4[3][3]);
        }
        // causal mask on diagonal tile
        if (j0 == q0) {
            #pragma unroll
            for (int rr = 0; rr < 4; rr++)
                #pragma unroll
                for (int cc = 0; cc < 4; cc++)
                    if (c0 + cc > r0 + rr) s4[rr][cc] = -1e30f;
        }
        #pragma unroll
        for (int rr = 0; rr < 4; rr++)
            #pragma unroll
            for (int cc = 0; cc < 4; cc++)
                Ss[(r0 + rr) * 65 + c0 + cc] = s4[rr][cc];
        __syncthreads();

        // online softmax stats: 4 threads per row
        {
            const int row = tid >> 2, part = tid & 3;
            float* srow = Ss + row * 65 + part * 16;
            float mx = -1e30f;
            #pragma unroll
            for (int j = 0; j < 16; j++) mx = fmaxf(mx, srow[j]);
            mx = fmaxf(mx, __shfl_xor_sync(0xffffffffu, mx, 1));
            mx = fmaxf(mx, __shfl_xor_sync(0xffffffffu, mx, 2));
            const float m_old = m_s[row];
            const float m_new = fmaxf(m_old, mx);
            float sum = 0.f;
            #pragma unroll
            for (int j = 0; j < 16; j++) {
                const float p = __expf(srow[j] - m_new);
                srow[j] = p;
                sum += p;
            }
            sum += __shfl_xor_sync(0xffffffffu, sum, 1);
            sum += __shfl_xor_sync(0xffffffffu, sum, 2);
            if (part == 0) {
                const float alpha = __expf(m_old - m_new);
                al_s[row] = alpha;
                m_s[row]  = m_new;
                l_s[row]  = l_s[row] * alpha + sum;
            }
        }
        __syncthreads();

        // O = O*alpha + P @ V
        const float a0 = al_s[r0 + 0], a1 = al_s[r0 + 1];
        const float a2 = al_s[r0 + 2], a3 = al_s[r0 + 3];
        #pragma unroll
        for (int cc = 0; cc < 4; cc++) {
            o[0][cc] *= a0; o[1][cc] *= a1; o[2][cc] *= a2; o[3][cc] *= a3;
        }
        #pragma unroll 8
        for (int j = 0; j < 64; j++) {
            const float4 vv = *reinterpret_cast<const float4*>(Vs + j * 64 + c0);
            const float p0 = Ss[(r0 + 0) * 65 + j];
            const float p1 = Ss[(r0 + 1) * 65 + j];
            const float p2 = Ss[(r0 + 2) * 65 + j];
            const float p3 = Ss[(r0 + 3) * 65 + j];
            o[0][0] = fmaf(p0, vv.x, o[0][0]); o[0][1] = fmaf(p0, vv.y, o[0][1]);
            o[0][2] = fmaf(p0, vv.z, o[0][2]); o[0][3] = fmaf(p0, vv.w, o[0][3]);
            o[1][0] = fmaf(p1, vv.x, o[1][0]); o[1][1] = fmaf(p1, vv.y, o[1][1]);
            o[1][2] = fmaf(p1, vv.z, o[1][2]); o[1][3] = fmaf(p1, vv.w, o[1][3]);
            o[2][0] = fmaf(p2, vv.x, o[2][0]); o[2][1] = fmaf(p2, vv.y, o[2][1]);
            o[2][2] = fmaf(p2, vv.z, o[2][2]); o[2][3] = fmaf(p2, vv.w, o[2][3]);
            o[3][0] = fmaf(p3, vv.x, o[3][0]); o[3][1] = fmaf(p3, vv.y, o[3][1]);
            o[3][2] = fmaf(p3, vv.z, o[3][2]); o[3][3] = fmaf(p3, vv.w, o[3][3]);
        }
    }

    // finalize and write y[B,T,C]
    #pragma unroll
    for (int rr = 0; rr < 4; rr++) {
        const float inv = 1.0f / l_s[r0 + rr];
        float4 ov = make_float4(o[rr][0] * inv, o[rr][1] * inv,
                                o[rr][2] * inv, o[rr][3] * inv);
        *reinterpret_cast<float4*>(
            y + ((size_t)bb * T + q0 + r0 + rr) * 1024 + hh * 64 + c0) = ov;
    }
}

// ---------------------------------------------------------------------------
// Launch
// ---------------------------------------------------------------------------
extern "C" void kernel_launch(void* const* d_in, const int* in_sizes, int n_in,
                              void* d_out, int out_size)
{
    const float* x      = (const float*)d_in[0];
    const float* ln1_g  = (const float*)d_in[1];
    const float* ln1_b  = (const float*)d_in[2];
    const float* W_attn = (const float*)d_in[3];
    const float* b_attn = (const float*)d_in[4];
    const float* W_o    = (const float*)d_in[5];
    const float* b_o    = (const float*)d_in[6];
    const float* ln2_g  = (const float*)d_in[7];
    const float* ln2_b  = (const float*)d_in[8];
    const float* W_fc   = (const float*)d_in[9];
    const float* b_fc   = (const float*)d_in[10];
    const float* W_fc2  = (const float*)d_in[11];
    const float* b_fc2  = (const float*)d_in[12];
    float* out = (float*)d_out;

    float *h, *qkv, *yb, *x1, *fc;
    cudaGetSymbolAddress((void**)&h,   g_h);
    cudaGetSymbolAddress((void**)&qkv, g_qkv);
    cudaGetSymbolAddress((void**)&yb,  g_y);
    cudaGetSymbolAddress((void**)&x1,  g_x1);
    cudaGetSymbolAddress((void**)&fc,  g_fc);

    const int ATTN_SMEM = 67584;
    cudaFuncSetAttribute(attn_kernel,
                         cudaFuncAttributeMaxDynamicSharedMemorySize, ATTN_SMEM);

    const int M = 4096;  // B*T

    // 1. LN1
    ln_kernel<<<M, 256>>>(x, ln1_g, ln1_b, h);
    // 2. QKV = h @ W_attn + b_attn   [4096, 3072]
    sgemm_kernel<0><<<dim3(3072 / 128, M / 128), 256>>>(
        h, W_attn, b_attn, nullptr, qkv, M, 3072, 1024);
    // 3. attention -> y [4096, 1024]
    attn_kernel<<<dim3(32, 32), 256, ATTN_SMEM>>>(qkv, yb);
    // 4. x1 = x + y @ W_o + b_o
    sgemm_kernel<1><<<dim3(1024 / 128, M / 128), 256>>>(
        yb, W_o, b_o, x, x1, M, 1024, 1024);
    // 5. LN2
    ln_kernel<<<M, 256>>>(x1, ln2_g, ln2_b, h);
    // 6. fc = gelu(h @ W_fc + b_fc)  [4096, 4096]
    sgemm_kernel<2><<<dim3(4096 / 128, M / 128), 256>>>(
        h, W_fc, b_fc, nullptr, fc, M, 4096, 1024);
    // 7. out = x1 + fc @ W_fc2 + b_fc2
    sgemm_kernel<1><<<dim3(1024 / 128, M / 128), 256>>>(
        fc, W_fc2, b_fc2, x1, out, M, 1024, 4096);
}